// round 8
// baseline (speedup 1.0000x reference)
#include <cuda_runtime.h>
#include <cuda_bf16.h>

// OHEM loss, C=1 specialization:
//   ce == 0 exactly, so cls_loss == 0; hard-negative mining is dead code.
//   out = 0.2 * sum_{pos}(smoothL1(loc_preds - loc_targets)) / num_pos
//
// R8: persistent CTAs + dynamic warp-level work stealing to kill the one-wave
// tail (DRAM busy stuck at ~73% across 7 static-schedule variants).
// Determinism: the TILE is the unit — each 256-anchor tile's partial uses a
// fixed intra-tile summation order and is identical no matter which warp
// computes it; the final fold walks tiles in fixed index order.

#define NBLOCKS   1184          // one wave at occ 8 (persistent)
#define NTHREADS  256
#define NWARPS    (NTHREADS / 32)
#define TILE      256           // anchors per warp-grab (8 per lane)
#define MAX_TILES 16384         // >= ceil(3.2M / 256) = 12500

__device__ float g_tile_sum[MAX_TILES];
__device__ int   g_tile_cnt[MAX_TILES];
__device__ int   g_work   = 0;    // dynamic tile counter (self-resets)
__device__ int   g_ticket = 0;    // block-exit ticket   (self-resets)

__device__ __forceinline__ float smooth_l1(float d) {
    float ax = fabsf(d);
    return (ax < 1.0f) ? 0.5f * d * d : ax - 0.5f;
}

__device__ __forceinline__ float anchor_loss(const float4* __restrict__ lp,
                                             const float4* __restrict__ lt,
                                             int i) {
    float4 p0 = __ldcs(lp + 2 * i);
    float4 p1 = __ldcs(lp + 2 * i + 1);
    float4 t0 = __ldcs(lt + 2 * i);
    float4 t1 = __ldcs(lt + 2 * i + 1);
    float s = smooth_l1(p0.x - t0.x);
    s += smooth_l1(p0.y - t0.y);
    s += smooth_l1(p0.z - t0.z);
    s += smooth_l1(p0.w - t0.w);
    s += smooth_l1(p1.x - t1.x);
    s += smooth_l1(p1.y - t1.y);
    s += smooth_l1(p1.z - t1.z);
    s += smooth_l1(p1.w - t1.w);
    return s;
}

__global__ __launch_bounds__(NTHREADS, 8)
void ohem_dynamic_kernel(const float4* __restrict__ lp,   // loc_preds
                         const float4* __restrict__ lt,   // loc_targets
                         const int*    __restrict__ ct,   // cls_targets
                         int nAnchors,
                         int nTiles,
                         float* __restrict__ out)
{
    const int lane = threadIdx.x & 31;
    const int wid  = threadIdx.x >> 5;

    // ---- dynamic warp-level tile loop ----
    for (;;) {
        int t;
        if (lane == 0) t = atomicAdd(&g_work, 1);
        t = __shfl_sync(0xFFFFFFFFu, t, 0);
        if (t >= nTiles) break;

        int base = t * TILE + lane;
        float s = 0.0f;
        int   c = 0;

        if (t * TILE + TILE <= nAnchors) {
            // full tile: front-batch all 8 ct loads, then predicated bodies
            int tv[8];
            #pragma unroll
            for (int k = 0; k < 8; k++) tv[k] = __ldcs(ct + base + k * 32);
            #pragma unroll
            for (int k = 0; k < 8; k++) {
                if (tv[k] > 0) { s += anchor_loss(lp, lt, base + k * 32); c++; }
            }
        } else {
            #pragma unroll
            for (int k = 0; k < 8; k++) {
                int i = base + k * 32;
                if (i < nAnchors) {
                    int tt = __ldcs(ct + i);
                    if (tt > 0) { s += anchor_loss(lp, lt, i); c++; }
                }
            }
        }

        // warp reduce (fixed tree order -> deterministic per tile)
        #pragma unroll
        for (int off = 16; off > 0; off >>= 1) {
            s += __shfl_xor_sync(0xFFFFFFFFu, s, off);
            c += __shfl_xor_sync(0xFFFFFFFFu, c, off);
        }
        if (lane == 0) {
            g_tile_sum[t] = s;
            g_tile_cnt[t] = c;
        }
    }

    // ---- block exit: ticket; last block folds tiles in fixed order ----
    __shared__ bool s_last;
    __syncthreads();                       // all warps' tile writes issued
    if (threadIdx.x == 0) {
        __threadfence();                   // publish this block's writes
        int ticket = atomicAdd(&g_ticket, 1);
        s_last = (ticket == gridDim.x - 1);
    }
    __syncthreads();

    if (s_last) {
        float fs = 0.0f;
        int   fc = 0;
        for (int k = threadIdx.x; k < nTiles; k += NTHREADS) {
            fs += ((volatile float*)g_tile_sum)[k];
            fc += ((volatile int*)g_tile_cnt)[k];
        }
        #pragma unroll
        for (int off = 16; off > 0; off >>= 1) {
            fs += __shfl_xor_sync(0xFFFFFFFFu, fs, off);
            fc += __shfl_xor_sync(0xFFFFFFFFu, fc, off);
        }
        __shared__ float ssum[NWARPS];
        __shared__ int   scnt[NWARPS];
        if (lane == 0) { ssum[wid] = fs; scnt[wid] = fc; }
        __syncthreads();
        if (wid == 0) {
            float s2 = (lane < NWARPS) ? ssum[lane] : 0.0f;
            int   c2 = (lane < NWARPS) ? scnt[lane] : 0;
            #pragma unroll
            for (int off = 16; off > 0; off >>= 1) {
                s2 += __shfl_xor_sync(0xFFFFFFFFu, s2, off);
                c2 += __shfl_xor_sync(0xFFFFFFFFu, c2, off);
            }
            if (lane == 0) {
                out[0] = 0.2f * s2 / (float)c2;  // cls term exactly 0 for C=1
                g_work   = 0;                    // reset for next graph replay
                g_ticket = 0;
            }
        }
    }
}

extern "C" void kernel_launch(void* const* d_in, const int* in_sizes, int n_in,
                              void* d_out, int out_size)
{
    // inputs: loc_preds [B,A,8] f32, loc_targets [B,A,8] f32,
    //         cls_preds [B,A,1] f32 (UNUSED), cls_targets [B,A] i32
    const float4* lp = (const float4*)d_in[0];
    const float4* lt = (const float4*)d_in[1];
    const int*    ct = (const int*)d_in[3];
    float* out = (float*)d_out;

    int nAnchors = in_sizes[3];                    // 3,200,000
    int nTiles   = (nAnchors + TILE - 1) / TILE;   // 12,500

    ohem_dynamic_kernel<<<NBLOCKS, NTHREADS>>>(lp, lt, ct, nAnchors, nTiles, out);
}

// round 9
// speedup vs baseline: 1.1389x; 1.1389x over previous
#include <cuda_runtime.h>
#include <cuda_bf16.h>

// OHEM loss, C=1 specialization:
//   ce == 0 exactly, so cls_loss == 0; hard-negative mining is dead code.
//   out = 0.2 * sum_{pos}(smoothL1(loc_preds - loc_targets)) / num_pos
//
// R9: multi-wave static contiguous chunking (2368 CTAs = 2 waves at occ 8).
// HW wave-2 rebalancing halves the CTA finish-time tail without any hot-loop
// atomics (R8 showed dynamic stealing overhead swamps the tail gain).
// Body = R6's best shape: 4-way front-batched ct, predicated __ldcs float4.
// Single kernel; last-arriving block folds partials (ticket + threadfence).

#define NBLOCKS  2368           // 148 SMs * 8 occ * 2 waves
#define NTHREADS 256
#define NWARPS   (NTHREADS / 32)
#define CHUNK    1352           // ceil(3.2M/2368) rounded to mult of 4 (128B lines)

__device__ float g_partial_sum[NBLOCKS];
__device__ int   g_partial_cnt[NBLOCKS];
__device__ int   g_ticket = 0;          // self-resets each run; deterministic

__device__ __forceinline__ float smooth_l1(float d) {
    float ax = fabsf(d);
    return (ax < 1.0f) ? 0.5f * d * d : ax - 0.5f;
}

__device__ __forceinline__ float anchor_loss(const float4* __restrict__ lp,
                                             const float4* __restrict__ lt,
                                             int i) {
    float4 p0 = __ldcs(lp + 2 * i);
    float4 p1 = __ldcs(lp + 2 * i + 1);
    float4 t0 = __ldcs(lt + 2 * i);
    float4 t1 = __ldcs(lt + 2 * i + 1);
    float s = smooth_l1(p0.x - t0.x);
    s += smooth_l1(p0.y - t0.y);
    s += smooth_l1(p0.z - t0.z);
    s += smooth_l1(p0.w - t0.w);
    s += smooth_l1(p1.x - t1.x);
    s += smooth_l1(p1.y - t1.y);
    s += smooth_l1(p1.z - t1.z);
    s += smooth_l1(p1.w - t1.w);
    return s;
}

__global__ __launch_bounds__(NTHREADS, 8)
void ohem_chunk_kernel(const float4* __restrict__ lp,   // loc_preds
                       const float4* __restrict__ lt,   // loc_targets
                       const int*    __restrict__ ct,   // cls_targets
                       int nAnchors,
                       float* __restrict__ out)
{
    float sum = 0.0f;
    int   cnt = 0;

    // contiguous chunk for this CTA
    const int start = blockIdx.x * CHUNK;
    const int end   = min(start + CHUNK, nAnchors);

    int i = start + threadIdx.x;
    // 4-way unrolled: all four ct loads issued before any body executes.
    for (; i + 3 * NTHREADS < end; i += 4 * NTHREADS) {
        int ta = __ldcs(ct + i);
        int tb = __ldcs(ct + i + NTHREADS);
        int tc = __ldcs(ct + i + 2 * NTHREADS);
        int td = __ldcs(ct + i + 3 * NTHREADS);
        if (ta > 0) { sum += anchor_loss(lp, lt, i);                cnt++; }
        if (tb > 0) { sum += anchor_loss(lp, lt, i + NTHREADS);     cnt++; }
        if (tc > 0) { sum += anchor_loss(lp, lt, i + 2 * NTHREADS); cnt++; }
        if (td > 0) { sum += anchor_loss(lp, lt, i + 3 * NTHREADS); cnt++; }
    }
    for (; i < end; i += NTHREADS) {
        int t = __ldcs(ct + i);
        if (t > 0) { sum += anchor_loss(lp, lt, i); cnt++; }
    }

    // intra-block tree reduction
    #pragma unroll
    for (int off = 16; off > 0; off >>= 1) {
        sum += __shfl_xor_sync(0xFFFFFFFFu, sum, off);
        cnt += __shfl_xor_sync(0xFFFFFFFFu, cnt, off);
    }

    __shared__ float ssum[NWARPS];
    __shared__ int   scnt[NWARPS];
    __shared__ bool  s_last;
    int lane = threadIdx.x & 31;
    int wid  = threadIdx.x >> 5;
    if (lane == 0) { ssum[wid] = sum; scnt[wid] = cnt; }
    __syncthreads();

    if (wid == 0) {
        float s = (lane < NWARPS) ? ssum[lane] : 0.0f;
        int   c = (lane < NWARPS) ? scnt[lane] : 0;
        #pragma unroll
        for (int off = 16; off > 0; off >>= 1) {
            s += __shfl_xor_sync(0xFFFFFFFFu, s, off);
            c += __shfl_xor_sync(0xFFFFFFFFu, c, off);
        }
        if (lane == 0) {
            g_partial_sum[blockIdx.x] = s;
            g_partial_cnt[blockIdx.x] = c;
            __threadfence();
            int ticket = atomicAdd(&g_ticket, 1);
            s_last = (ticket == gridDim.x - 1);
        }
    }
    __syncthreads();

    // last-arriving block folds all partials (fixed tree order: deterministic)
    if (s_last) {
        float fs = 0.0f;
        int   fc = 0;
        for (int k = threadIdx.x; k < NBLOCKS; k += NTHREADS) {
            fs += ((volatile float*)g_partial_sum)[k];
            fc += ((volatile int*)g_partial_cnt)[k];
        }
        #pragma unroll
        for (int off = 16; off > 0; off >>= 1) {
            fs += __shfl_xor_sync(0xFFFFFFFFu, fs, off);
            fc += __shfl_xor_sync(0xFFFFFFFFu, fc, off);
        }
        if (lane == 0) { ssum[wid] = fs; scnt[wid] = fc; }
        __syncthreads();
        if (wid == 0) {
            float s2 = (lane < NWARPS) ? ssum[lane] : 0.0f;
            int   c2 = (lane < NWARPS) ? scnt[lane] : 0;
            #pragma unroll
            for (int off = 16; off > 0; off >>= 1) {
                s2 += __shfl_xor_sync(0xFFFFFFFFu, s2, off);
                c2 += __shfl_xor_sync(0xFFFFFFFFu, c2, off);
            }
            if (lane == 0) {
                out[0] = 0.2f * s2 / (float)c2;   // cls term exactly 0 for C=1
                g_ticket = 0;                     // reset for next graph replay
            }
        }
    }
}

extern "C" void kernel_launch(void* const* d_in, const int* in_sizes, int n_in,
                              void* d_out, int out_size)
{
    // inputs: loc_preds [B,A,8] f32, loc_targets [B,A,8] f32,
    //         cls_preds [B,A,1] f32 (UNUSED), cls_targets [B,A] i32
    const float4* lp = (const float4*)d_in[0];
    const float4* lt = (const float4*)d_in[1];
    const int*    ct = (const int*)d_in[3];
    float* out = (float*)d_out;

    int nAnchors = in_sizes[3];      // 3,200,000

    ohem_chunk_kernel<<<NBLOCKS, NTHREADS>>>(lp, lt, ct, nAnchors, out);
}

// round 10
// speedup vs baseline: 1.2551x; 1.1020x over previous
#include <cuda_runtime.h>
#include <cuda_bf16.h>

// OHEM loss, C=1 specialization:
//   ce == 0 exactly, so cls_loss == 0; hard-negative mining is dead code.
//   out = 0.2 * sum_{pos}(smoothL1(loc_preds - loc_targets)) / num_pos
//
// Converged design (best of 9 structural variants = R6):
//   one-wave grid-stride (all CTAs sweep the address space in lock-step ->
//   uniform L2-slice/HBM-channel load), __ldcs evict-first streaming,
//   predicated per-anchor float4 bodies (keeps the 6% 128B-line-skip saving),
//   in-kernel ticket finalize. R10 refinement: 8-way ct front-batching.

#define NBLOCKS  1184           // 148 SMs * 8 blocks -> exactly one wave
#define NTHREADS 256
#define NWARPS   (NTHREADS / 32)

__device__ float g_partial_sum[NBLOCKS];
__device__ int   g_partial_cnt[NBLOCKS];
__device__ int   g_ticket = 0;          // self-resets each run; deterministic

__device__ __forceinline__ float smooth_l1(float d) {
    float ax = fabsf(d);
    return (ax < 1.0f) ? 0.5f * d * d : ax - 0.5f;
}

__device__ __forceinline__ float anchor_loss(const float4* __restrict__ lp,
                                             const float4* __restrict__ lt,
                                             int i) {
    float4 p0 = __ldcs(lp + 2 * i);
    float4 p1 = __ldcs(lp + 2 * i + 1);
    float4 t0 = __ldcs(lt + 2 * i);
    float4 t1 = __ldcs(lt + 2 * i + 1);
    float s = smooth_l1(p0.x - t0.x);
    s += smooth_l1(p0.y - t0.y);
    s += smooth_l1(p0.z - t0.z);
    s += smooth_l1(p0.w - t0.w);
    s += smooth_l1(p1.x - t1.x);
    s += smooth_l1(p1.y - t1.y);
    s += smooth_l1(p1.z - t1.z);
    s += smooth_l1(p1.w - t1.w);
    return s;
}

__global__ __launch_bounds__(NTHREADS, 8)
void ohem_fused_kernel(const float4* __restrict__ lp,   // loc_preds  (2 float4/anchor)
                       const float4* __restrict__ lt,   // loc_targets
                       const int*    __restrict__ ct,   // cls_targets
                       int nAnchors,
                       float* __restrict__ out)
{
    float sum = 0.0f;
    int   cnt = 0;

    const int stride  = gridDim.x * blockDim.x;
    const int stride8 = 8 * stride;
    int i = blockIdx.x * blockDim.x + threadIdx.x;

    // 8-way unrolled: all eight ct loads issued before any body executes.
    for (; i + 7 * stride < nAnchors; i += stride8) {
        int tv[8];
        #pragma unroll
        for (int k = 0; k < 8; k++) tv[k] = __ldcs(ct + i + k * stride);
        #pragma unroll
        for (int k = 0; k < 8; k++) {
            if (tv[k] > 0) { sum += anchor_loss(lp, lt, i + k * stride); cnt++; }
        }
    }
    for (; i < nAnchors; i += stride) {
        int t = __ldcs(ct + i);
        if (t > 0) { sum += anchor_loss(lp, lt, i); cnt++; }
    }

    // intra-block tree reduction
    #pragma unroll
    for (int off = 16; off > 0; off >>= 1) {
        sum += __shfl_xor_sync(0xFFFFFFFFu, sum, off);
        cnt += __shfl_xor_sync(0xFFFFFFFFu, cnt, off);
    }

    __shared__ float ssum[NWARPS];
    __shared__ int   scnt[NWARPS];
    __shared__ bool  s_last;
    int lane = threadIdx.x & 31;
    int wid  = threadIdx.x >> 5;
    if (lane == 0) { ssum[wid] = sum; scnt[wid] = cnt; }
    __syncthreads();

    if (wid == 0) {
        float s = (lane < NWARPS) ? ssum[lane] : 0.0f;
        int   c = (lane < NWARPS) ? scnt[lane] : 0;
        #pragma unroll
        for (int off = 16; off > 0; off >>= 1) {
            s += __shfl_xor_sync(0xFFFFFFFFu, s, off);
            c += __shfl_xor_sync(0xFFFFFFFFu, c, off);
        }
        if (lane == 0) {
            g_partial_sum[blockIdx.x] = s;
            g_partial_cnt[blockIdx.x] = c;
            __threadfence();
            int ticket = atomicAdd(&g_ticket, 1);
            s_last = (ticket == gridDim.x - 1);
        }
    }
    __syncthreads();

    // last-arriving block folds all partials (fixed tree order: deterministic)
    if (s_last) {
        float fs = 0.0f;
        int   fc = 0;
        for (int k = threadIdx.x; k < NBLOCKS; k += NTHREADS) {
            fs += ((volatile float*)g_partial_sum)[k];
            fc += ((volatile int*)g_partial_cnt)[k];
        }
        #pragma unroll
        for (int off = 16; off > 0; off >>= 1) {
            fs += __shfl_xor_sync(0xFFFFFFFFu, fs, off);
            fc += __shfl_xor_sync(0xFFFFFFFFu, fc, off);
        }
        if (lane == 0) { ssum[wid] = fs; scnt[wid] = fc; }
        __syncthreads();
        if (wid == 0) {
            float s2 = (lane < NWARPS) ? ssum[lane] : 0.0f;
            int   c2 = (lane < NWARPS) ? scnt[lane] : 0;
            #pragma unroll
            for (int off = 16; off > 0; off >>= 1) {
                s2 += __shfl_xor_sync(0xFFFFFFFFu, s2, off);
                c2 += __shfl_xor_sync(0xFFFFFFFFu, c2, off);
            }
            if (lane == 0) {
                out[0] = 0.2f * s2 / (float)c2;   // cls term exactly 0 for C=1
                g_ticket = 0;                     // reset for next graph replay
            }
        }
    }
}

extern "C" void kernel_launch(void* const* d_in, const int* in_sizes, int n_in,
                              void* d_out, int out_size)
{
    // inputs: loc_preds [B,A,8] f32, loc_targets [B,A,8] f32,
    //         cls_preds [B,A,1] f32 (UNUSED), cls_targets [B,A] i32
    const float4* lp = (const float4*)d_in[0];
    const float4* lt = (const float4*)d_in[1];
    const int*    ct = (const int*)d_in[3];
    float* out = (float*)d_out;

    int nAnchors = in_sizes[3];      // 3,200,000

    ohem_fused_kernel<<<NBLOCKS, NTHREADS>>>(lp, lt, ct, nAnchors, out);
}

// round 11
// speedup vs baseline: 1.2801x; 1.0199x over previous
#include <cuda_runtime.h>
#include <cuda_bf16.h>

// OHEM loss, C=1 specialization (FINAL — converged after 10 variants):
//   ce == 0 exactly (logsumexp over singleton axis minus the gathered element),
//   so cls_loss == 0 and the hard-negative mining is dead code.
//   out = 0.2 * sum_{pos}(smoothL1(loc_preds - loc_targets)) / num_pos
//
// Measured invariants (R1-R10): traffic floor ~209 MB (128B line granularity;
// predication saves only the 6% all-negative lines); streaming plateau
// 5.8 TB/s / 73% DRAM busy regardless of MLP depth, load width, cache hints,
// or schedule. Best shape: one-wave grid-stride (uniform L2/HBM channel load),
// 4-way front-batched ct, predicated __ldcs float4 bodies, in-kernel ticket
// finalize. ~36 us kernel, ~37.4 us end-to-end, rel_err 0.

#define NBLOCKS  1184   // 148 SMs * 8 blocks -> exactly one wave
#define NTHREADS 256
#define NWARPS   (NTHREADS / 32)

__device__ float g_partial_sum[NBLOCKS];
__device__ int   g_partial_cnt[NBLOCKS];
__device__ int   g_ticket = 0;          // self-resets each run; deterministic

__device__ __forceinline__ float smooth_l1(float d) {
    float ax = fabsf(d);
    return (ax < 1.0f) ? 0.5f * d * d : ax - 0.5f;
}

__device__ __forceinline__ float anchor_loss_cs(const float4* __restrict__ lp,
                                                const float4* __restrict__ lt,
                                                int i) {
    // Evict-first streaming loads: data is read exactly once.
    float4 p0 = __ldcs(lp + 2 * i);
    float4 p1 = __ldcs(lp + 2 * i + 1);
    float4 t0 = __ldcs(lt + 2 * i);
    float4 t1 = __ldcs(lt + 2 * i + 1);
    float s = smooth_l1(p0.x - t0.x);
    s += smooth_l1(p0.y - t0.y);
    s += smooth_l1(p0.z - t0.z);
    s += smooth_l1(p0.w - t0.w);
    s += smooth_l1(p1.x - t1.x);
    s += smooth_l1(p1.y - t1.y);
    s += smooth_l1(p1.z - t1.z);
    s += smooth_l1(p1.w - t1.w);
    return s;
}

__global__ __launch_bounds__(NTHREADS, 8)
void ohem_fused_kernel(const float4* __restrict__ lp,   // loc_preds  (2 float4/anchor)
                       const float4* __restrict__ lt,   // loc_targets
                       const int*    __restrict__ ct,   // cls_targets
                       int nAnchors,
                       float* __restrict__ out)
{
    float sum = 0.0f;
    int   cnt = 0;

    const int stride  = gridDim.x * blockDim.x;
    const int stride4 = 4 * stride;
    int i = blockIdx.x * blockDim.x + threadIdx.x;

    // 4-way unrolled: all four ct loads issued before any body executes.
    for (; i + 3 * stride < nAnchors; i += stride4) {
        int ta = __ldcs(ct + i);
        int tb = __ldcs(ct + i + stride);
        int tc = __ldcs(ct + i + 2 * stride);
        int td = __ldcs(ct + i + 3 * stride);
        if (ta > 0) { sum += anchor_loss_cs(lp, lt, i);              cnt++; }
        if (tb > 0) { sum += anchor_loss_cs(lp, lt, i + stride);     cnt++; }
        if (tc > 0) { sum += anchor_loss_cs(lp, lt, i + 2 * stride); cnt++; }
        if (td > 0) { sum += anchor_loss_cs(lp, lt, i + 3 * stride); cnt++; }
    }
    for (; i < nAnchors; i += stride) {
        int t = __ldcs(ct + i);
        if (t > 0) { sum += anchor_loss_cs(lp, lt, i); cnt++; }
    }

    // intra-block tree reduction
    #pragma unroll
    for (int off = 16; off > 0; off >>= 1) {
        sum += __shfl_xor_sync(0xFFFFFFFFu, sum, off);
        cnt += __shfl_xor_sync(0xFFFFFFFFu, cnt, off);
    }

    __shared__ float ssum[NWARPS];
    __shared__ int   scnt[NWARPS];
    __shared__ bool  s_last;
    int lane = threadIdx.x & 31;
    int wid  = threadIdx.x >> 5;
    if (lane == 0) { ssum[wid] = sum; scnt[wid] = cnt; }
    __syncthreads();

    if (wid == 0) {
        float s = (lane < NWARPS) ? ssum[lane] : 0.0f;
        int   c = (lane < NWARPS) ? scnt[lane] : 0;
        #pragma unroll
        for (int off = 16; off > 0; off >>= 1) {
            s += __shfl_xor_sync(0xFFFFFFFFu, s, off);
            c += __shfl_xor_sync(0xFFFFFFFFu, c, off);
        }
        if (lane == 0) {
            g_partial_sum[blockIdx.x] = s;
            g_partial_cnt[blockIdx.x] = c;
            __threadfence();
            int ticket = atomicAdd(&g_ticket, 1);
            s_last = (ticket == gridDim.x - 1);
        }
    }
    __syncthreads();

    // last-arriving block folds all partials (fixed tree order: deterministic)
    if (s_last) {
        float fs = 0.0f;
        int   fc = 0;
        for (int k = threadIdx.x; k < NBLOCKS; k += NTHREADS) {
            fs += ((volatile float*)g_partial_sum)[k];
            fc += ((volatile int*)g_partial_cnt)[k];
        }
        #pragma unroll
        for (int off = 16; off > 0; off >>= 1) {
            fs += __shfl_xor_sync(0xFFFFFFFFu, fs, off);
            fc += __shfl_xor_sync(0xFFFFFFFFu, fc, off);
        }
        if (lane == 0) { ssum[wid] = fs; scnt[wid] = fc; }
        __syncthreads();
        if (wid == 0) {
            float s2 = (lane < NWARPS) ? ssum[lane] : 0.0f;
            int   c2 = (lane < NWARPS) ? scnt[lane] : 0;
            #pragma unroll
            for (int off = 16; off > 0; off >>= 1) {
                s2 += __shfl_xor_sync(0xFFFFFFFFu, s2, off);
                c2 += __shfl_xor_sync(0xFFFFFFFFu, c2, off);
            }
            if (lane == 0) {
                out[0] = 0.2f * s2 / (float)c2;   // cls term exactly 0 for C=1
                g_ticket = 0;                     // reset for next graph replay
            }
        }
    }
}

extern "C" void kernel_launch(void* const* d_in, const int* in_sizes, int n_in,
                              void* d_out, int out_size)
{
    // inputs: loc_preds [B,A,8] f32, loc_targets [B,A,8] f32,
    //         cls_preds [B,A,1] f32 (UNUSED), cls_targets [B,A] i32
    const float4* lp = (const float4*)d_in[0];
    const float4* lt = (const float4*)d_in[1];
    const int*    ct = (const int*)d_in[3];
    float* out = (float*)d_out;

    int nAnchors = in_sizes[3];      // 3,200,000

    ohem_fused_kernel<<<NBLOCKS, NTHREADS>>>(lp, lt, ct, nAnchors, out);
}